// round 16
// baseline (speedup 1.0000x reference)
#include <cuda_runtime.h>
#include <cuda_fp16.h>
#include <cstdint>
#include <math.h>

// Problem constants
#define T_TOK 8192
#define D_DIM 1024
#define E_NUM 8
#define F_DIM 4096
#define CAP   1280
#define TK    (T_TOK*2)
#define EC    (E_NUM*CAP)

// fused prologue block ranges (block 0 = rank/aux block, then the ranges below)
#define NB_GATE 1024
#define NB_W13  16384
#define NB_W2   16384
#define NB_ZY   8192
#define NB_PRE  (1 + NB_GATE + NB_W13 + NB_W2 + NB_ZY)

// ---------------- scratch (static device globals; zero-initialized at load) ----
__device__ __align__(16) int   g_expert[TK];
__device__ float g_w[TK];
__device__ __align__(16) int   g_row_token[EC];
__device__ float g_row_w[EC];
__device__ int   g_cnt[E_NUM];
__device__ float g_prob[E_NUM];
__device__ int   g_gate_done;
__device__ __align__(16) __half g_xh[(size_t)T_TOK * D_DIM];
__device__ __align__(16) __half g_w13h[(size_t)E_NUM * 2 * F_DIM * D_DIM];
__device__ __align__(16) __half g_w2h[(size_t)E_NUM * D_DIM * F_DIM];
__device__ __align__(16) __half g_hbuf[(size_t)EC * F_DIM];

// ---------------- PTX helpers -------------------------------------------------
__device__ __forceinline__ uint32_t smem_u32(const void* p) {
    uint32_t a;
    asm("{ .reg .u64 t; cvta.to.shared.u64 t, %1; cvt.u32.u64 %0, t; }" : "=r"(a) : "l"(p));
    return a;
}
#define SWZ(o) ((uint32_t)(o) ^ ((((uint32_t)(o)) >> 3) & 0x70u))

__device__ __forceinline__ void cpa16(uint32_t dst, const void* src, uint32_t sz) {
    asm volatile("cp.async.cg.shared.global [%0], [%1], 16, %2;"
                 :: "r"(dst), "l"(src), "r"(sz));
}
__device__ __forceinline__ void cp_commit() { asm volatile("cp.async.commit_group;"); }
#define CP_WAIT1() asm volatile("cp.async.wait_group 1;")
#define CP_WAIT2() asm volatile("cp.async.wait_group 2;")

__device__ __forceinline__ void ldsm4(uint32_t& r0, uint32_t& r1, uint32_t& r2, uint32_t& r3,
                                      uint32_t a) {
    asm volatile("ldmatrix.sync.aligned.m8n8.x4.shared.b16 {%0,%1,%2,%3}, [%4];"
                 : "=r"(r0), "=r"(r1), "=r"(r2), "=r"(r3) : "r"(a));
}
__device__ __forceinline__ void mma16816(float* c, const uint32_t* a, uint32_t b0, uint32_t b1) {
    asm volatile(
        "mma.sync.aligned.m16n8k16.row.col.f32.f16.f16.f32 "
        "{%0,%1,%2,%3},{%4,%5,%6,%7},{%8,%9},{%0,%1,%2,%3};"
        : "+f"(c[0]), "+f"(c[1]), "+f"(c[2]), "+f"(c[3])
        : "r"(a[0]), "r"(a[1]), "r"(a[2]), "r"(a[3]), "r"(b0), "r"(b1));
}
__device__ __forceinline__ uint32_t f22u(float a, float b) {
    __half2 h = __floats2half2_rn(a, b);
    return *reinterpret_cast<uint32_t*>(&h);
}
__device__ __forceinline__ uint4 pack8(float4 a, float4 b) {
    return make_uint4(f22u(a.x, a.y), f22u(a.z, a.w), f22u(b.x, b.y), f22u(b.z, b.w));
}
__device__ __forceinline__ int ld_acq(const int* p) {
    int v;
    asm volatile("ld.acquire.gpu.b32 %0, [%1];" : "=r"(v) : "l"(p));
    return v;
}

// ---------------- kernel 1: fused prologue (rank block first) -------------------
__global__ void __launch_bounds__(256) fused_pre(const float* __restrict__ x,
                                                 const float* __restrict__ gw,
                                                 const float* __restrict__ w1,
                                                 const float* __restrict__ w3,
                                                 const float* __restrict__ w2,
                                                 float* __restrict__ y,
                                                 int aux_idx) {
    __shared__ float sgw[E_NUM * D_DIM];
    __shared__ int   scnt[E_NUM];
    __shared__ float sprob[E_NUM];
    __shared__ unsigned long long wt0[8], wt1[8];
    int b = blockIdx.x;
    int tid = threadIdx.x;

    if (b == 0) {
        // ---- rank + aux block: resident from wave 1, overlaps conv blocks ----
        const int PER = TK / 256;   // 64 slots/thread, streamed twice (low regs)
        int lane = tid & 31, warp = tid >> 5;

        if (tid == 0) {
            while (ld_acq(&g_gate_done) < NB_GATE) { }
        }
        __syncthreads();
        __threadfence();

        if (tid == 0) {
            float s = 0.f;
#pragma unroll
            for (int e = 0; e < E_NUM; e++)
                s += ((float)g_cnt[e] / (float)T_TOK) * (g_prob[e] / (float)T_TOK);
            y[aux_idx] = 0.01f * (float)E_NUM * s;
#pragma unroll
            for (int e = 0; e < E_NUM; e++) { g_cnt[e] = 0; g_prob[e] = 0.f; }
            g_gate_done = 0;
        }

        for (int i = tid; i < EC / 4; i += 256)
            ((int4*)g_row_token)[i] = make_int4(-1, -1, -1, -1);

        const int4* gex = (const int4*)g_expert + (size_t)tid * (PER / 4);

        // pass 1: packed per-thread counts (values not retained)
        unsigned long long p0 = 0, p1 = 0;
        for (int v = 0; v < PER / 4; v++) {
            int4 q = gex[v];
            int es[4] = {q.x, q.y, q.z, q.w};
#pragma unroll
            for (int j = 0; j < 4; j++) {
                int e = es[j];
                if (e < 4) p0 += 1ull << (16 * e);
                else       p1 += 1ull << (16 * (e - 4));
            }
        }
        unsigned long long i0 = p0, i1 = p1;
#pragma unroll
        for (int off = 1; off < 32; off <<= 1) {
            unsigned long long t0 = __shfl_up_sync(0xffffffffu, i0, off);
            unsigned long long t1 = __shfl_up_sync(0xffffffffu, i1, off);
            if (lane >= off) { i0 += t0; i1 += t1; }
        }
        if (lane == 31) { wt0[warp] = i0; wt1[warp] = i1; }
        __syncthreads();
        if (warp == 0 && lane < 8) {
            unsigned long long o0 = wt0[lane], o1 = wt1[lane];
            unsigned long long a0 = o0, a1 = o1;
#pragma unroll
            for (int off = 1; off < 8; off <<= 1) {
                unsigned long long t0 = __shfl_up_sync(0x000000ffu, a0, off);
                unsigned long long t1 = __shfl_up_sync(0x000000ffu, a1, off);
                if (lane >= off) { a0 += t0; a1 += t1; }
            }
            wt0[lane] = a0 - o0;
            wt1[lane] = a1 - o1;
        }
        __syncthreads();
        unsigned long long e0 = i0 - p0 + wt0[warp];
        unsigned long long e1 = i1 - p1 + wt1[warp];
        int cnt[E_NUM];
#pragma unroll
        for (int e = 0; e < 4; e++) cnt[e]     = (int)((e0 >> (16 * e)) & 0xffff);
#pragma unroll
        for (int e = 0; e < 4; e++) cnt[4 + e] = (int)((e1 >> (16 * e)) & 0xffff);

        // pass 2: re-stream and scatter
        int base = tid * PER;
        for (int v = 0; v < PER / 4; v++) {
            int4 q = gex[v];
            int es[4] = {q.x, q.y, q.z, q.w};
#pragma unroll
            for (int j = 0; j < 4; j++) {
                int slot = base + v * 4 + j;
                int e = es[j];
                int r = cnt[e]++;
                if (r < CAP) {
                    g_row_token[e * CAP + r] = slot >> 1;
                    g_row_w[e * CAP + r] = g_w[slot];
                }
            }
        }
    } else if (b <= NB_GATE) {
        // ---- gating + x->fp16 (register-diet: 4 floats/iter, no unroll) ----
        for (int i = tid; i < E_NUM * D_DIM; i += 256) sgw[i] = gw[i];
        if (tid < E_NUM) { scnt[tid] = 0; sprob[tid] = 0.f; }
        __syncthreads();

        int warp = tid >> 5, lane = tid & 31;
        int t = (b - 1) * 8 + warp;

        float acc[E_NUM];
#pragma unroll
        for (int e = 0; e < E_NUM; e++) acc[e] = 0.f;
        const float* xr = x + (size_t)t * D_DIM;
        __half* xhr = g_xh + (size_t)t * D_DIM;
#pragma unroll 1
        for (int it = 0; it < 8; it++) {
            int d4 = it * 32 + lane;               // 4-float group index
            float4 a = *(const float4*)(xr + d4 * 4);
            *(uint2*)(xhr + d4 * 4) = make_uint2(f22u(a.x, a.y), f22u(a.z, a.w));
            int d = d4 * 4;
#pragma unroll
            for (int e = 0; e < E_NUM; e++) {
                float s = fmaf(a.x, sgw[e * D_DIM + d], acc[e]);
                s = fmaf(a.y, sgw[e * D_DIM + d + 1], s);
                s = fmaf(a.z, sgw[e * D_DIM + d + 2], s);
                acc[e] = fmaf(a.w, sgw[e * D_DIM + d + 3], s);
            }
        }
#pragma unroll
        for (int e = 0; e < E_NUM; e++) {
#pragma unroll
            for (int off = 16; off; off >>= 1)
                acc[e] += __shfl_xor_sync(0xffffffffu, acc[e], off);
        }

        if (lane == 0) {
            float m = acc[0];
#pragma unroll
            for (int e = 1; e < E_NUM; e++) m = fmaxf(m, acc[e]);
            float p[E_NUM], s = 0.f;
#pragma unroll
            for (int e = 0; e < E_NUM; e++) { p[e] = __expf(acc[e] - m); s += p[e]; }
            float inv = 1.f / s;
#pragma unroll
            for (int e = 0; e < E_NUM; e++) atomicAdd(&sprob[e], p[e] * inv);
            int i0 = 0;
#pragma unroll
            for (int e = 1; e < E_NUM; e++) if (acc[e] > acc[i0]) i0 = e;
            int i1 = -1;
#pragma unroll
            for (int e = 0; e < E_NUM; e++) {
                if (e == i0) continue;
                if (i1 < 0 || acc[e] > acc[i1]) i1 = e;
            }
            float w0 = 1.f / (1.f + __expf(acc[i1] - acc[i0]));
            g_expert[2 * t] = i0;  g_expert[2 * t + 1] = i1;
            g_w[2 * t] = w0;       g_w[2 * t + 1] = 1.f - w0;
            atomicAdd(&scnt[i0], 1);
            atomicAdd(&scnt[i1], 1);
        }
        __syncthreads();
        if (tid < E_NUM) {
            atomicAdd(&g_cnt[tid], scnt[tid]);
            atomicAdd(&g_prob[tid], sprob[tid]);
        }
        __syncthreads();
        if (tid == 0) {
            __threadfence();                      // release
            atomicAdd(&g_gate_done, 1);
        }
    } else if (b <= NB_GATE + NB_W13) {
        // ---- conv w1/w3 (interleaved) ----
        size_t i8 = (size_t)(b - 1 - NB_GATE) * 256 + tid;
        size_t row = i8 >> 7;
        int d8 = (int)(i8 & 127);
        size_t e = row >> 12;
        size_t f = row & 4095;
        const float4* p1 = (const float4*)w1 + i8 * 2;
        const float4* p3 = (const float4*)w3 + i8 * 2;
        size_t b1 = ((e * 2 * F_DIM) + 2 * f) * D_DIM + (size_t)d8 * 8;
        *(uint4*)(g_w13h + b1)         = pack8(p1[0], p1[1]);
        *(uint4*)(g_w13h + b1 + D_DIM) = pack8(p3[0], p3[1]);
    } else if (b <= NB_GATE + NB_W13 + NB_W2) {
        // ---- conv w2 ----
        size_t i8 = (size_t)(b - 1 - NB_GATE - NB_W13) * 256 + tid;
        const float4* p = (const float4*)w2 + i8 * 2;
        *(uint4*)(g_w2h + i8 * 8) = pack8(p[0], p[1]);
    } else {
        // ---- zero y ----
        size_t i = (size_t)(b - 1 - NB_GATE - NB_W13 - NB_W2) * 256 + tid;
        ((float4*)y)[i] = make_float4(0.f, 0.f, 0.f, 0.f);
    }
}

// ---------------- kernel 2: GEMM1 (mma.sync fp16) + fused SwiGLU ----------------
#define STAGE1   49152
#define G1_SMEM  (4 * STAGE1)    // 192 KB
#define NSTEP1   (D_DIM / 64)

__global__ void __launch_bounds__(512, 1) gemm1_mma() {
    extern __shared__ char smem[];
    uint32_t sb = smem_u32(smem);
    int tid = threadIdx.x, lane = tid & 31, warp = tid >> 5;
    int e = blockIdx.z, m0 = blockIdx.y * 256, nh0 = blockIdx.x * 64;

    const char* srcA[4]; uint32_t szA[4], oA[4];
    const char* srcB[2]; uint32_t oB[2];
#pragma unroll
    for (int j = 0; j < 4; j++) {
        int c = j * 512 + tid;
        int r = c >> 3;
        int cb = (c & 7) * 16;
        int tok = g_row_token[e * CAP + m0 + r];
        szA[j] = (tok >= 0) ? 16u : 0u;
        srcA[j] = (const char*)(g_xh + (size_t)(tok < 0 ? 0 : tok) * D_DIM) + cb;
        oA[j] = SWZ(r * 128 + cb);
    }
#pragma unroll
    for (int j = 0; j < 2; j++) {
        int c = j * 512 + tid;
        int r = c >> 3;
        int cb = (c & 7) * 16;
        srcB[j] = (const char*)(g_w13h + ((size_t)e * 2 * F_DIM + (size_t)nh0 * 2 + r) * D_DIM) + cb;
        oB[j] = 32768u + SWZ(r * 128 + cb);
    }

    float acc[4][4][4];
#pragma unroll
    for (int i = 0; i < 4; i++)
#pragma unroll
        for (int j = 0; j < 4; j++)
#pragma unroll
            for (int q = 0; q < 4; q++) acc[i][j][q] = 0.f;

    int wm = warp & 3, wn = warp >> 2;
    uint32_t aRow = wm * 64 + (lane & 15);
    uint32_t aK   = (lane >> 4) * 16;
    uint32_t bRow = wn * 32 + (lane & 7) + ((lane >> 4) & 1) * 8;
    uint32_t bK   = ((lane >> 3) & 1) * 16;

#pragma unroll
    for (int s = 0; s < 3; s++) {
        uint32_t b = sb + s * STAGE1;
#pragma unroll
        for (int j = 0; j < 4; j++) cpa16(b + oA[j], srcA[j] + s * 128, szA[j]);
#pragma unroll
        for (int j = 0; j < 2; j++) cpa16(b + oB[j], srcB[j] + s * 128, 16u);
        cp_commit();
    }

    for (int step = 0; step < NSTEP1; step++) {
        CP_WAIT2();
        __syncthreads();
        {
            int s = step + 3;
            if (s < NSTEP1) {
                uint32_t b = sb + (s & 3) * STAGE1;
#pragma unroll
                for (int j = 0; j < 4; j++) cpa16(b + oA[j], srcA[j] + s * 128, szA[j]);
#pragma unroll
                for (int j = 0; j < 2; j++) cpa16(b + oB[j], srcB[j] + s * 128, 16u);
            }
            cp_commit();
        }
        uint32_t bb = sb + (step & 3) * STAGE1;
#pragma unroll
        for (int c16 = 0; c16 < 4; c16++) {
            uint32_t kb = c16 * 32;
            uint32_t a[4][4], brg[2][4];
#pragma unroll
            for (int mt = 0; mt < 4; mt++)
                ldsm4(a[mt][0], a[mt][1], a[mt][2], a[mt][3],
                      bb + SWZ((aRow + mt * 16) * 128 + kb + aK));
#pragma unroll
            for (int bt = 0; bt < 2; bt++)
                ldsm4(brg[bt][0], brg[bt][1], brg[bt][2], brg[bt][3],
                      bb + 32768u + SWZ((bRow + bt * 16) * 128 + kb + bK));
#pragma unroll
            for (int mt = 0; mt < 4; mt++)
#pragma unroll
                for (int nt = 0; nt < 4; nt++)
                    mma16816(acc[mt][nt], a[mt], brg[nt >> 1][(nt & 1) * 2],
                             brg[nt >> 1][(nt & 1) * 2 + 1]);
        }
    }

    __syncthreads();
#pragma unroll
    for (int mt = 0; mt < 4; mt++)
#pragma unroll
        for (int nt = 0; nt < 4; nt++) {
            int row = wm * 64 + mt * 16 + (lane >> 2);
            int col = wn * 16 + nt * 4 + (lane & 3);
            float g0 = acc[mt][nt][0], v0 = acc[mt][nt][1];
            float g1 = acc[mt][nt][2], v1 = acc[mt][nt][3];
            float h0 = (g0 / (1.f + __expf(-g0))) * v0;
            float h1 = (g1 / (1.f + __expf(-g1))) * v1;
            *(__half*)(smem + row * 128 + col * 2)       = __float2half_rn(h0);
            *(__half*)(smem + (row + 8) * 128 + col * 2) = __float2half_rn(h1);
        }
    __syncthreads();
#pragma unroll
    for (int j = 0; j < 4; j++) {
        int c = j * 512 + tid;
        int r = c >> 3;
        int cb = (c & 7) * 16;
        *(uint4*)((char*)(g_hbuf + ((size_t)(e * CAP + m0 + r)) * F_DIM + nh0) + cb) =
            *(uint4*)(smem + r * 128 + cb);
    }
}

// ---------------- kernel 3: GEMM2 (M=128,N=128, occ 2, K-split 2) + combine -----
#define STAGE2   32768
#define G2_SMEM  (3 * STAGE2)
#define KSPLIT   2
#define KHALF    (F_DIM / KSPLIT)     // 2048
#define NSTEP2   (KHALF / 64)         // 32

__global__ void __launch_bounds__(256, 2) gemm2_mma(float* __restrict__ y) {
    extern __shared__ char smem[];
    uint32_t sb = smem_u32(smem);
    int tid = threadIdx.x, lane = tid & 31, warp = tid >> 5;
    int e = blockIdx.z;
    int m0 = (blockIdx.y >> 1) * 128;
    int ks = blockIdx.y & 1;
    int n0 = blockIdx.x * 128;

    const char* srcA[4]; uint32_t oA[4];
    const char* srcB[4]; uint32_t oB[4];
#pragma unroll
    for (int j = 0; j < 4; j++) {
        int c = j * 256 + tid;
        int r = c >> 3;
        int cb = (c & 7) * 16;
        srcA[j] = (const char*)(g_hbuf + (size_t)(e * CAP + m0 + r) * F_DIM + ks * KHALF) + cb;
        oA[j] = SWZ(r * 128 + cb);
        srcB[j] = (const char*)(g_w2h + ((size_t)e * D_DIM + n0 + r) * F_DIM + ks * KHALF) + cb;
        oB[j] = 16384u + SWZ(r * 128 + cb);
    }

    float acc[4][4][4];
#pragma unroll
    for (int i = 0; i < 4; i++)
#pragma unroll
        for (int j = 0; j < 4; j++)
#pragma unroll
            for (int q = 0; q < 4; q++) acc[i][j][q] = 0.f;

    int wm = warp & 1, wn = warp >> 1;
    uint32_t aRow = wm * 64 + (lane & 15);
    uint32_t aK   = (lane >> 4) * 16;
    uint32_t bRow = wn * 32 + (lane & 7) + ((lane >> 4) & 1) * 8;
    uint32_t bK   = ((lane >> 3) & 1) * 16;

#pragma unroll
    for (int s = 0; s < 2; s++) {
        uint32_t b = sb + s * STAGE2;
#pragma unroll
        for (int j = 0; j < 4; j++) {
            cpa16(b + oA[j], srcA[j] + s * 128, 16u);
            cpa16(b + oB[j], srcB[j] + s * 128, 16u);
        }
        cp_commit();
    }

    for (int step = 0; step < NSTEP2; step++) {
        CP_WAIT1();
        __syncthreads();
        {
            int s = step + 2;
            if (s < NSTEP2) {
                uint32_t b = sb + (s % 3) * STAGE2;
#pragma unroll
                for (int j = 0; j < 4; j++) {
                    cpa16(b + oA[j], srcA[j] + (size_t)s * 128, 16u);
                    cpa16(b + oB[j], srcB[j] + (size_t)s * 128, 16u);
                }
            }
            cp_commit();
        }
        uint32_t bb = sb + (step % 3) * STAGE2;
#pragma unroll
        for (int c16 = 0; c16 < 4; c16++) {
            uint32_t kb = c16 * 32;
            uint32_t a[4][4], brg[2][4];
#pragma unroll
            for (int mt = 0; mt < 4; mt++)
                ldsm4(a[mt][0], a[mt][1], a[mt][2], a[mt][3],
                      bb + SWZ((aRow + mt * 16) * 128 + kb + aK));
#pragma unroll
            for (int bt = 0; bt < 2; bt++)
                ldsm4(brg[bt][0], brg[bt][1], brg[bt][2], brg[bt][3],
                      bb + 16384u + SWZ((bRow + bt * 16) * 128 + kb + bK));
#pragma unroll
            for (int mt = 0; mt < 4; mt++)
#pragma unroll
                for (int nt = 0; nt < 4; nt++)
                    mma16816(acc[mt][nt], a[mt], brg[nt >> 1][(nt & 1) * 2],
                             brg[nt >> 1][(nt & 1) * 2 + 1]);
        }
    }

    // epilogue: weighted scatter-add into y (each y element: 2 slots x 2 k-splits)
#pragma unroll
    for (int mt = 0; mt < 4; mt++) {
        int rl0 = wm * 64 + mt * 16 + (lane >> 2);
        int gr0 = e * CAP + m0 + rl0;
        int gr1 = gr0 + 8;
        int t0 = g_row_token[gr0];
        int t1 = g_row_token[gr1];
        float w0 = g_row_w[gr0], w1 = g_row_w[gr1];
#pragma unroll
        for (int nt = 0; nt < 4; nt++) {
            int col = n0 + wn * 32 + nt * 8 + (lane & 3) * 2;
            if (t0 >= 0) {
                float* p = y + (size_t)t0 * D_DIM + col;
                atomicAdd(p,     w0 * acc[mt][nt][0]);
                atomicAdd(p + 1, w0 * acc[mt][nt][1]);
            }
            if (t1 >= 0) {
                float* p = y + (size_t)t1 * D_DIM + col;
                atomicAdd(p,     w1 * acc[mt][nt][2]);
                atomicAdd(p + 1, w1 * acc[mt][nt][3]);
            }
        }
    }
}

// ---------------- launch ---------------------------------------------------------
extern "C" void kernel_launch(void* const* d_in, const int* in_sizes, int n_in,
                              void* d_out, int out_size) {
    const float* x  = (const float*)d_in[0];
    const float* gw = (const float*)d_in[1];
    const float* w1 = (const float*)d_in[2];
    const float* w3 = (const float*)d_in[3];
    const float* w2 = (const float*)d_in[4];
    float* y = (float*)d_out;

    cudaFuncSetAttribute(gemm1_mma, cudaFuncAttributeMaxDynamicSharedMemorySize, G1_SMEM);
    cudaFuncSetAttribute(gemm2_mma, cudaFuncAttributeMaxDynamicSharedMemorySize, G2_SMEM);

    fused_pre<<<NB_PRE, 256>>>(x, gw, w1, w3, w2, y, out_size - 1);
    gemm1_mma<<<dim3(F_DIM / 64, CAP / 256, E_NUM), 512, G1_SMEM>>>();
    gemm2_mma<<<dim3(D_DIM / 128, (CAP / 128) * KSPLIT, E_NUM), 256, G2_SMEM>>>(y);
}

// round 17
// speedup vs baseline: 1.0136x; 1.0136x over previous
#include <cuda_runtime.h>
#include <cuda_fp16.h>
#include <cstdint>
#include <math.h>

// Problem constants
#define T_TOK 8192
#define D_DIM 1024
#define E_NUM 8
#define F_DIM 4096
#define CAP   1280
#define TK    (T_TOK*2)
#define EC    (E_NUM*CAP)

// fused prologue block ranges (block 0 = rank/aux block, then the ranges below)
#define NB_GATE 1024
#define NB_W13  16384
#define NB_W2   16384
#define NB_ZY   8192
#define NB_PRE  (1 + NB_GATE + NB_W13 + NB_W2 + NB_ZY)

// ---------------- scratch (static device globals; zero-initialized at load) ----
__device__ __align__(16) int   g_expert[TK];
__device__ float g_w[TK];
__device__ __align__(16) int   g_row_token[EC];
__device__ float g_row_w[EC];
__device__ int   g_cnt[E_NUM];
__device__ float g_prob[E_NUM];
__device__ int   g_gate_done;
__device__ __align__(16) __half g_xh[(size_t)T_TOK * D_DIM];
__device__ __align__(16) __half g_w13h[(size_t)E_NUM * 2 * F_DIM * D_DIM];
__device__ __align__(16) __half g_w2h[(size_t)E_NUM * D_DIM * F_DIM];
__device__ __align__(16) __half g_hbuf[(size_t)EC * F_DIM];

// ---------------- PTX helpers -------------------------------------------------
__device__ __forceinline__ uint32_t smem_u32(const void* p) {
    uint32_t a;
    asm("{ .reg .u64 t; cvta.to.shared.u64 t, %1; cvt.u32.u64 %0, t; }" : "=r"(a) : "l"(p));
    return a;
}
#define SWZ(o) ((uint32_t)(o) ^ ((((uint32_t)(o)) >> 3) & 0x70u))

__device__ __forceinline__ void cpa16(uint32_t dst, const void* src, uint32_t sz) {
    asm volatile("cp.async.cg.shared.global [%0], [%1], 16, %2;"
                 :: "r"(dst), "l"(src), "r"(sz));
}
__device__ __forceinline__ void cp_commit() { asm volatile("cp.async.commit_group;"); }
#define CP_WAIT1() asm volatile("cp.async.wait_group 1;")
#define CP_WAIT2() asm volatile("cp.async.wait_group 2;")

__device__ __forceinline__ void ldsm4(uint32_t& r0, uint32_t& r1, uint32_t& r2, uint32_t& r3,
                                      uint32_t a) {
    asm volatile("ldmatrix.sync.aligned.m8n8.x4.shared.b16 {%0,%1,%2,%3}, [%4];"
                 : "=r"(r0), "=r"(r1), "=r"(r2), "=r"(r3) : "r"(a));
}
__device__ __forceinline__ void mma16816(float* c, const uint32_t* a, uint32_t b0, uint32_t b1) {
    asm volatile(
        "mma.sync.aligned.m16n8k16.row.col.f32.f16.f16.f32 "
        "{%0,%1,%2,%3},{%4,%5,%6,%7},{%8,%9},{%0,%1,%2,%3};"
        : "+f"(c[0]), "+f"(c[1]), "+f"(c[2]), "+f"(c[3])
        : "r"(a[0]), "r"(a[1]), "r"(a[2]), "r"(a[3]), "r"(b0), "r"(b1));
}
__device__ __forceinline__ uint32_t f22u(float a, float b) {
    __half2 h = __floats2half2_rn(a, b);
    return *reinterpret_cast<uint32_t*>(&h);
}
__device__ __forceinline__ uint4 pack8(float4 a, float4 b) {
    return make_uint4(f22u(a.x, a.y), f22u(a.z, a.w), f22u(b.x, b.y), f22u(b.z, b.w));
}
__device__ __forceinline__ int ld_acq(const int* p) {
    int v;
    asm volatile("ld.acquire.gpu.b32 %0, [%1];" : "=r"(v) : "l"(p));
    return v;
}

// ---------------- kernel 1: fused prologue (rank block first) -------------------
__global__ void __launch_bounds__(256, 3) fused_pre(const float* __restrict__ x,
                                                    const float* __restrict__ gw,
                                                    const float* __restrict__ w1,
                                                    const float* __restrict__ w3,
                                                    const float* __restrict__ w2,
                                                    float* __restrict__ y,
                                                    int aux_idx) {
    __shared__ float sgw[E_NUM * D_DIM];
    __shared__ int   scnt[E_NUM];
    __shared__ float sprob[E_NUM];
    __shared__ unsigned long long wt0[8], wt1[8];
    int b = blockIdx.x;
    int tid = threadIdx.x;

    if (b == 0) {
        // ---- rank + aux block: resident from wave 1, overlaps conv blocks ----
        const int PER = TK / 256;   // 64 slots/thread, streamed twice (low regs)
        int lane = tid & 31, warp = tid >> 5;

        if (tid == 0) {
            while (ld_acq(&g_gate_done) < NB_GATE) { }
        }
        __syncthreads();
        __threadfence();

        if (tid == 0) {
            float s = 0.f;
#pragma unroll
            for (int e = 0; e < E_NUM; e++)
                s += ((float)g_cnt[e] / (float)T_TOK) * (g_prob[e] / (float)T_TOK);
            y[aux_idx] = 0.01f * (float)E_NUM * s;
#pragma unroll
            for (int e = 0; e < E_NUM; e++) { g_cnt[e] = 0; g_prob[e] = 0.f; }
            g_gate_done = 0;
        }

        for (int i = tid; i < EC / 4; i += 256)
            ((int4*)g_row_token)[i] = make_int4(-1, -1, -1, -1);

        const int4* gex = (const int4*)g_expert + (size_t)tid * (PER / 4);

        // pass 1: packed per-thread counts (values not retained)
        unsigned long long p0 = 0, p1 = 0;
        for (int v = 0; v < PER / 4; v++) {
            int4 q = gex[v];
            int es[4] = {q.x, q.y, q.z, q.w};
#pragma unroll
            for (int j = 0; j < 4; j++) {
                int e = es[j];
                if (e < 4) p0 += 1ull << (16 * e);
                else       p1 += 1ull << (16 * (e - 4));
            }
        }
        unsigned long long i0 = p0, i1 = p1;
#pragma unroll
        for (int off = 1; off < 32; off <<= 1) {
            unsigned long long t0 = __shfl_up_sync(0xffffffffu, i0, off);
            unsigned long long t1 = __shfl_up_sync(0xffffffffu, i1, off);
            if (lane >= off) { i0 += t0; i1 += t1; }
        }
        if (lane == 31) { wt0[warp] = i0; wt1[warp] = i1; }
        __syncthreads();
        if (warp == 0 && lane < 8) {
            unsigned long long o0 = wt0[lane], o1 = wt1[lane];
            unsigned long long a0 = o0, a1 = o1;
#pragma unroll
            for (int off = 1; off < 8; off <<= 1) {
                unsigned long long t0 = __shfl_up_sync(0x000000ffu, a0, off);
                unsigned long long t1 = __shfl_up_sync(0x000000ffu, a1, off);
                if (lane >= off) { a0 += t0; a1 += t1; }
            }
            wt0[lane] = a0 - o0;
            wt1[lane] = a1 - o1;
        }
        __syncthreads();
        unsigned long long e0 = i0 - p0 + wt0[warp];
        unsigned long long e1 = i1 - p1 + wt1[warp];
        int cnt[E_NUM];
#pragma unroll
        for (int e = 0; e < 4; e++) cnt[e]     = (int)((e0 >> (16 * e)) & 0xffff);
#pragma unroll
        for (int e = 0; e < 4; e++) cnt[4 + e] = (int)((e1 >> (16 * e)) & 0xffff);

        // pass 2: re-stream and scatter
        int base = tid * PER;
        for (int v = 0; v < PER / 4; v++) {
            int4 q = gex[v];
            int es[4] = {q.x, q.y, q.z, q.w};
#pragma unroll
            for (int j = 0; j < 4; j++) {
                int slot = base + v * 4 + j;
                int e = es[j];
                int r = cnt[e]++;
                if (r < CAP) {
                    g_row_token[e * CAP + r] = slot >> 1;
                    g_row_w[e * CAP + r] = g_w[slot];
                }
            }
        }
    } else if (b <= NB_GATE) {
        // ---- gating + x->fp16 ----
        for (int i = tid; i < E_NUM * D_DIM; i += 256) sgw[i] = gw[i];
        if (tid < E_NUM) { scnt[tid] = 0; sprob[tid] = 0.f; }
        __syncthreads();

        int warp = tid >> 5, lane = tid & 31;
        int t = (b - 1) * 8 + warp;

        float acc[E_NUM];
#pragma unroll
        for (int e = 0; e < E_NUM; e++) acc[e] = 0.f;
        const float* xr = x + (size_t)t * D_DIM;
        __half* xhr = g_xh + (size_t)t * D_DIM;
#pragma unroll
        for (int it = 0; it < 4; it++) {
            int d8 = it * 32 + lane;
            float4 a = *(const float4*)(xr + d8 * 8);
            float4 bb = *(const float4*)(xr + d8 * 8 + 4);
            *(uint4*)(xhr + d8 * 8) = pack8(a, bb);
            float v[8] = {a.x, a.y, a.z, a.w, bb.x, bb.y, bb.z, bb.w};
#pragma unroll
            for (int q = 0; q < 8; q++) {
                int d = d8 * 8 + q;
#pragma unroll
                for (int e = 0; e < E_NUM; e++) acc[e] = fmaf(v[q], sgw[e * D_DIM + d], acc[e]);
            }
        }
#pragma unroll
        for (int e = 0; e < E_NUM; e++) {
#pragma unroll
            for (int off = 16; off; off >>= 1)
                acc[e] += __shfl_xor_sync(0xffffffffu, acc[e], off);
        }

        if (lane == 0) {
            float m = acc[0];
#pragma unroll
            for (int e = 1; e < E_NUM; e++) m = fmaxf(m, acc[e]);
            float p[E_NUM], s = 0.f;
#pragma unroll
            for (int e = 0; e < E_NUM; e++) { p[e] = __expf(acc[e] - m); s += p[e]; }
            float inv = 1.f / s;
#pragma unroll
            for (int e = 0; e < E_NUM; e++) atomicAdd(&sprob[e], p[e] * inv);
            int i0 = 0;
#pragma unroll
            for (int e = 1; e < E_NUM; e++) if (acc[e] > acc[i0]) i0 = e;
            int i1 = -1;
#pragma unroll
            for (int e = 0; e < E_NUM; e++) {
                if (e == i0) continue;
                if (i1 < 0 || acc[e] > acc[i1]) i1 = e;
            }
            float w0 = 1.f / (1.f + __expf(acc[i1] - acc[i0]));
            g_expert[2 * t] = i0;  g_expert[2 * t + 1] = i1;
            g_w[2 * t] = w0;       g_w[2 * t + 1] = 1.f - w0;
            atomicAdd(&scnt[i0], 1);
            atomicAdd(&scnt[i1], 1);
        }
        __syncthreads();
        if (tid < E_NUM) {
            atomicAdd(&g_cnt[tid], scnt[tid]);
            atomicAdd(&g_prob[tid], sprob[tid]);
        }
        __syncthreads();
        if (tid == 0) {
            __threadfence();                      // release
            atomicAdd(&g_gate_done, 1);
        }
    } else if (b <= NB_GATE + NB_W13) {
        // ---- conv w1/w3 (interleaved), streaming source reads ----
        size_t i8 = (size_t)(b - 1 - NB_GATE) * 256 + tid;
        size_t row = i8 >> 7;
        int d8 = (int)(i8 & 127);
        size_t e = row >> 12;
        size_t f = row & 4095;
        float4 a1 = __ldcs((const float4*)w1 + i8 * 2);
        float4 b1v = __ldcs((const float4*)w1 + i8 * 2 + 1);
        float4 a3 = __ldcs((const float4*)w3 + i8 * 2);
        float4 b3v = __ldcs((const float4*)w3 + i8 * 2 + 1);
        size_t o1 = ((e * 2 * F_DIM) + 2 * f) * D_DIM + (size_t)d8 * 8;
        *(uint4*)(g_w13h + o1)         = pack8(a1, b1v);
        *(uint4*)(g_w13h + o1 + D_DIM) = pack8(a3, b3v);
    } else if (b <= NB_GATE + NB_W13 + NB_W2) {
        // ---- conv w2, streaming source reads ----
        size_t i8 = (size_t)(b - 1 - NB_GATE - NB_W13) * 256 + tid;
        float4 a = __ldcs((const float4*)w2 + i8 * 2);
        float4 bv = __ldcs((const float4*)w2 + i8 * 2 + 1);
        *(uint4*)(g_w2h + i8 * 8) = pack8(a, bv);
    } else {
        // ---- zero y ----
        size_t i = (size_t)(b - 1 - NB_GATE - NB_W13 - NB_W2) * 256 + tid;
        ((float4*)y)[i] = make_float4(0.f, 0.f, 0.f, 0.f);
    }
}

// ---------------- kernel 2: GEMM1 (mma.sync fp16) + fused SwiGLU ----------------
#define STAGE1   49152
#define G1_SMEM  (4 * STAGE1)    // 192 KB
#define NSTEP1   (D_DIM / 64)

__global__ void __launch_bounds__(512, 1) gemm1_mma() {
    extern __shared__ char smem[];
    uint32_t sb = smem_u32(smem);
    int tid = threadIdx.x, lane = tid & 31, warp = tid >> 5;
    int e = blockIdx.z, m0 = blockIdx.y * 256, nh0 = blockIdx.x * 64;

    const char* srcA[4]; uint32_t szA[4], oA[4];
    const char* srcB[2]; uint32_t oB[2];
#pragma unroll
    for (int j = 0; j < 4; j++) {
        int c = j * 512 + tid;
        int r = c >> 3;
        int cb = (c & 7) * 16;
        int tok = g_row_token[e * CAP + m0 + r];
        szA[j] = (tok >= 0) ? 16u : 0u;
        srcA[j] = (const char*)(g_xh + (size_t)(tok < 0 ? 0 : tok) * D_DIM) + cb;
        oA[j] = SWZ(r * 128 + cb);
    }
#pragma unroll
    for (int j = 0; j < 2; j++) {
        int c = j * 512 + tid;
        int r = c >> 3;
        int cb = (c & 7) * 16;
        srcB[j] = (const char*)(g_w13h + ((size_t)e * 2 * F_DIM + (size_t)nh0 * 2 + r) * D_DIM) + cb;
        oB[j] = 32768u + SWZ(r * 128 + cb);
    }

    float acc[4][4][4];
#pragma unroll
    for (int i = 0; i < 4; i++)
#pragma unroll
        for (int j = 0; j < 4; j++)
#pragma unroll
            for (int q = 0; q < 4; q++) acc[i][j][q] = 0.f;

    int wm = warp & 3, wn = warp >> 2;
    uint32_t aRow = wm * 64 + (lane & 15);
    uint32_t aK   = (lane >> 4) * 16;
    uint32_t bRow = wn * 32 + (lane & 7) + ((lane >> 4) & 1) * 8;
    uint32_t bK   = ((lane >> 3) & 1) * 16;

#pragma unroll
    for (int s = 0; s < 3; s++) {
        uint32_t b = sb + s * STAGE1;
#pragma unroll
        for (int j = 0; j < 4; j++) cpa16(b + oA[j], srcA[j] + s * 128, szA[j]);
#pragma unroll
        for (int j = 0; j < 2; j++) cpa16(b + oB[j], srcB[j] + s * 128, 16u);
        cp_commit();
    }

    for (int step = 0; step < NSTEP1; step++) {
        CP_WAIT2();
        __syncthreads();
        {
            int s = step + 3;
            if (s < NSTEP1) {
                uint32_t b = sb + (s & 3) * STAGE1;
#pragma unroll
                for (int j = 0; j < 4; j++) cpa16(b + oA[j], srcA[j] + s * 128, szA[j]);
#pragma unroll
                for (int j = 0; j < 2; j++) cpa16(b + oB[j], srcB[j] + s * 128, 16u);
            }
            cp_commit();
        }
        uint32_t bb = sb + (step & 3) * STAGE1;
#pragma unroll
        for (int c16 = 0; c16 < 4; c16++) {
            uint32_t kb = c16 * 32;
            uint32_t a[4][4], brg[2][4];
#pragma unroll
            for (int mt = 0; mt < 4; mt++)
                ldsm4(a[mt][0], a[mt][1], a[mt][2], a[mt][3],
                      bb + SWZ((aRow + mt * 16) * 128 + kb + aK));
#pragma unroll
            for (int bt = 0; bt < 2; bt++)
                ldsm4(brg[bt][0], brg[bt][1], brg[bt][2], brg[bt][3],
                      bb + 32768u + SWZ((bRow + bt * 16) * 128 + kb + bK));
#pragma unroll
            for (int mt = 0; mt < 4; mt++)
#pragma unroll
                for (int nt = 0; nt < 4; nt++)
                    mma16816(acc[mt][nt], a[mt], brg[nt >> 1][(nt & 1) * 2],
                             brg[nt >> 1][(nt & 1) * 2 + 1]);
        }
    }

    __syncthreads();
#pragma unroll
    for (int mt = 0; mt < 4; mt++)
#pragma unroll
        for (int nt = 0; nt < 4; nt++) {
            int row = wm * 64 + mt * 16 + (lane >> 2);
            int col = wn * 16 + nt * 4 + (lane & 3);
            float g0 = acc[mt][nt][0], v0 = acc[mt][nt][1];
            float g1 = acc[mt][nt][2], v1 = acc[mt][nt][3];
            float h0 = (g0 / (1.f + __expf(-g0))) * v0;
            float h1 = (g1 / (1.f + __expf(-g1))) * v1;
            *(__half*)(smem + row * 128 + col * 2)       = __float2half_rn(h0);
            *(__half*)(smem + (row + 8) * 128 + col * 2) = __float2half_rn(h1);
        }
    __syncthreads();
#pragma unroll
    for (int j = 0; j < 4; j++) {
        int c = j * 512 + tid;
        int r = c >> 3;
        int cb = (c & 7) * 16;
        *(uint4*)((char*)(g_hbuf + ((size_t)(e * CAP + m0 + r)) * F_DIM + nh0) + cb) =
            *(uint4*)(smem + r * 128 + cb);
    }
}

// ---------------- kernel 3: GEMM2 (M=128,N=128, occ 2, K-split 2) + combine -----
#define STAGE2   32768
#define G2_SMEM  (3 * STAGE2)
#define KSPLIT   2
#define KHALF    (F_DIM / KSPLIT)     // 2048
#define NSTEP2   (KHALF / 64)         // 32

__global__ void __launch_bounds__(256, 2) gemm2_mma(float* __restrict__ y) {
    extern __shared__ char smem[];
    uint32_t sb = smem_u32(smem);
    int tid = threadIdx.x, lane = tid & 31, warp = tid >> 5;
    int e = blockIdx.z;
    int m0 = (blockIdx.y >> 1) * 128;
    int ks = blockIdx.y & 1;
    int n0 = blockIdx.x * 128;

    const char* srcA[4]; uint32_t oA[4];
    const char* srcB[4]; uint32_t oB[4];
#pragma unroll
    for (int j = 0; j < 4; j++) {
        int c = j * 256 + tid;
        int r = c >> 3;
        int cb = (c & 7) * 16;
        srcA[j] = (const char*)(g_hbuf + (size_t)(e * CAP + m0 + r) * F_DIM + ks * KHALF) + cb;
        oA[j] = SWZ(r * 128 + cb);
        srcB[j] = (const char*)(g_w2h + ((size_t)e * D_DIM + n0 + r) * F_DIM + ks * KHALF) + cb;
        oB[j] = 16384u + SWZ(r * 128 + cb);
    }

    float acc[4][4][4];
#pragma unroll
    for (int i = 0; i < 4; i++)
#pragma unroll
        for (int j = 0; j < 4; j++)
#pragma unroll
            for (int q = 0; q < 4; q++) acc[i][j][q] = 0.f;

    int wm = warp & 1, wn = warp >> 1;
    uint32_t aRow = wm * 64 + (lane & 15);
    uint32_t aK   = (lane >> 4) * 16;
    uint32_t bRow = wn * 32 + (lane & 7) + ((lane >> 4) & 1) * 8;
    uint32_t bK   = ((lane >> 3) & 1) * 16;

#pragma unroll
    for (int s = 0; s < 2; s++) {
        uint32_t b = sb + s * STAGE2;
#pragma unroll
        for (int j = 0; j < 4; j++) {
            cpa16(b + oA[j], srcA[j] + s * 128, 16u);
            cpa16(b + oB[j], srcB[j] + s * 128, 16u);
        }
        cp_commit();
    }

    for (int step = 0; step < NSTEP2; step++) {
        CP_WAIT1();
        __syncthreads();
        {
            int s = step + 2;
            if (s < NSTEP2) {
                uint32_t b = sb + (s % 3) * STAGE2;
#pragma unroll
                for (int j = 0; j < 4; j++) {
                    cpa16(b + oA[j], srcA[j] + (size_t)s * 128, 16u);
                    cpa16(b + oB[j], srcB[j] + (size_t)s * 128, 16u);
                }
            }
            cp_commit();
        }
        uint32_t bb = sb + (step % 3) * STAGE2;
#pragma unroll
        for (int c16 = 0; c16 < 4; c16++) {
            uint32_t kb = c16 * 32;
            uint32_t a[4][4], brg[2][4];
#pragma unroll
            for (int mt = 0; mt < 4; mt++)
                ldsm4(a[mt][0], a[mt][1], a[mt][2], a[mt][3],
                      bb + SWZ((aRow + mt * 16) * 128 + kb + aK));
#pragma unroll
            for (int bt = 0; bt < 2; bt++)
                ldsm4(brg[bt][0], brg[bt][1], brg[bt][2], brg[bt][3],
                      bb + 16384u + SWZ((bRow + bt * 16) * 128 + kb + bK));
#pragma unroll
            for (int mt = 0; mt < 4; mt++)
#pragma unroll
                for (int nt = 0; nt < 4; nt++)
                    mma16816(acc[mt][nt], a[mt], brg[nt >> 1][(nt & 1) * 2],
                             brg[nt >> 1][(nt & 1) * 2 + 1]);
        }
    }

    // epilogue: weighted scatter-add into y (each y element: 2 slots x 2 k-splits)
#pragma unroll
    for (int mt = 0; mt < 4; mt++) {
        int rl0 = wm * 64 + mt * 16 + (lane >> 2);
        int gr0 = e * CAP + m0 + rl0;
        int gr1 = gr0 + 8;
        int t0 = g_row_token[gr0];
        int t1 = g_row_token[gr1];
        float w0 = g_row_w[gr0], w1 = g_row_w[gr1];
#pragma unroll
        for (int nt = 0; nt < 4; nt++) {
            int col = n0 + wn * 32 + nt * 8 + (lane & 3) * 2;
            if (t0 >= 0) {
                float* p = y + (size_t)t0 * D_DIM + col;
                atomicAdd(p,     w0 * acc[mt][nt][0]);
                atomicAdd(p + 1, w0 * acc[mt][nt][1]);
            }
            if (t1 >= 0) {
                float* p = y + (size_t)t1 * D_DIM + col;
                atomicAdd(p,     w1 * acc[mt][nt][2]);
                atomicAdd(p + 1, w1 * acc[mt][nt][3]);
            }
        }
    }
}

// ---------------- launch ---------------------------------------------------------
extern "C" void kernel_launch(void* const* d_in, const int* in_sizes, int n_in,
                              void* d_out, int out_size) {
    const float* x  = (const float*)d_in[0];
    const float* gw = (const float*)d_in[1];
    const float* w1 = (const float*)d_in[2];
    const float* w3 = (const float*)d_in[3];
    const float* w2 = (const float*)d_in[4];
    float* y = (float*)d_out;

    cudaFuncSetAttribute(gemm1_mma, cudaFuncAttributeMaxDynamicSharedMemorySize, G1_SMEM);
    cudaFuncSetAttribute(gemm2_mma, cudaFuncAttributeMaxDynamicSharedMemorySize, G2_SMEM);

    fused_pre<<<NB_PRE, 256>>>(x, gw, w1, w3, w2, y, out_size - 1);
    gemm1_mma<<<dim3(F_DIM / 64, CAP / 256, E_NUM), 512, G1_SMEM>>>();
    gemm2_mma<<<dim3(D_DIM / 128, (CAP / 128) * KSPLIT, E_NUM), 256, G2_SMEM>>>(y);
}